// round 13
// baseline (speedup 1.0000x reference)
#include <cuda_runtime.h>
#include <math.h>

// ---------------------------------------------------------------------------
// SplatPushModel2 — 1 memset + 2 kernels, single stream:
//   memset  : zero accumulators (device symbol, graph-capturable)
//   k_swept : out = occ*(1-swept), fused m_swept accumulation. LTS-bound
//             (~18.8us = 6300 B/cyc L2 cap — done).
//   k_tail  : ONE resident kernel (128 blk x 256 thr) for everything else:
//             existing -> [gridbar] -> dep_sum -> [gridbar] -> deposit
//             blur+add tiles. No intermediate launches/edges.
// Sigmoid cutoff CUT=10 -> propagated error ~1e-5 rel (tolerance 1e-3).
// ---------------------------------------------------------------------------

#define NB    16
#define HW    1024
#define IMG   (HW*HW)
#define SBLK  8                  // tail blocks per batch
#define STOT  (SBLK*NB)          // 128 — all resident (<=148 SMs)

__device__ __constant__ float KW[9] = {
    0.00761439f, 0.03607498f, 0.10958593f, 0.21344431f, 0.26655960f,
    0.21344431f, 0.10958593f, 0.03607498f, 0.00761439f
};

// [0..NB) m_swept, [NB..2NB) existing, [2NB..3NB) dep_sum
__device__ float g_acc[3*NB];
__device__ unsigned g_cnt = 0;   // barrier arrivals (self-resets)
__device__ unsigned g_gen = 0;   // barrier generation (monotonic, replay-safe)

struct Geo { float p0x, p0y, p1x, p1y, ux, uy, L; };

__device__ __forceinline__ float clampf(float v, float lo, float hi) {
    return fminf(fmaxf(v, lo), hi);
}

__device__ __forceinline__ Geo makeGeo(const float* as_, const float* ae_, int b) {
    Geo g;
    g.p0x = as_[b*3+0]; g.p0y = as_[b*3+1];
    g.p1x = ae_[b*3+0]; g.p1y = ae_[b*3+1];
    float dx = g.p1x - g.p0x, dy = g.p1y - g.p0y;
    g.L = sqrtf(dx*dx + dy*dy + 1e-8f);
    float inv = __fdividef(1.0f, g.L);
    g.ux = dx*inv; g.uy = dy*inv;
    return g;
}

// ---------------- k_swept: big image pass + m_swept accumulation ------------
__global__ __launch_bounds__(256) void k_swept(const float* __restrict__ occ,
                                               const float* __restrict__ as_,
                                               const float* __restrict__ ae_,
                                               float* __restrict__ out) {
    const float WIDTH = 3.0f, CUT = 10.0f, EPS = 1e-8f;
    int b  = blockIdx.z;
    int w0 = blockIdx.x << 7;
    int h0 = blockIdx.y << 5;
    Geo g = makeGeo(as_, ae_, b);

    float cx = w0 + 63.5f, cy = h0 + 15.5f;
    float rxc = cx - g.p0x, ryc = cy - g.p0y;
    float tc  = clampf(rxc*g.ux + ryc*g.uy, 0.f, g.L);
    float dcx = rxc - tc*g.ux, dcy = ryc - tc*g.uy;
    float Rt  = WIDTH + CUT + 66.5f;
    bool sw_act = (dcx*dcx + dcy*dcy) < Rt*Rt;

    int t  = threadIdx.x;
    int lw = (t & 31) << 2;
    int lh = t >> 5;
    int gi = b*IMG + (h0 + lh)*HW + (w0 + lw);

    float4 v[4];
    #pragma unroll
    for (int k = 0; k < 4; k++)
        v[k] = __ldcs((const float4*)(occ + gi + k*8*HW));

    if (!sw_act) {
        #pragma unroll
        for (int k = 0; k < 4; k++)
            __stcs((float4*)(out + gi + k*8*HW), v[k]);
        return;
    }

    float acc = 0.f;
    #pragma unroll
    for (int k = 0; k < 4; k++) {
        float y  = (float)(h0 + lh + k*8);
        float ry = y - g.p0y;
        float o[4];
        float* in = (float*)&v[k];
        #pragma unroll
        for (int j = 0; j < 4; j++) {
            float x  = (float)(w0 + lw + j);
            float rx = x - g.p0x;
            float tt = clampf(rx*g.ux + ry*g.uy, 0.f, g.L);
            float ddx = rx - tt*g.ux, ddy = ry - tt*g.uy;
            float d2 = ddx*ddx + ddy*ddy + EPS;
            float R0 = WIDTH + CUT;
            float sw = 0.f;
            if (d2 < R0*R0) {
                float dist = d2 * rsqrtf(d2);
                sw = __fdividef(1.f, 1.f + __expf(dist - WIDTH));
            }
            acc += in[j] * sw;
            o[j] = in[j] * (1.f - sw);
        }
        __stcs((float4*)(out + gi + k*8*HW), make_float4(o[0], o[1], o[2], o[3]));
    }

    __shared__ float sred[8];
    #pragma unroll
    for (int o = 16; o > 0; o >>= 1) acc += __shfl_down_sync(0xffffffffu, acc, o);
    int lane = t & 31, wp = t >> 5;
    if (lane == 0) sred[wp] = acc;
    __syncthreads();
    if (t == 0) {
        float s = 0.f;
        #pragma unroll
        for (int i = 0; i < 8; i++) s += sred[i];
        if (s != 0.f) atomicAdd(&g_acc[b], s);
    }
}

// ------------- helpers -------------------------------------------------------
__device__ __forceinline__ bool rowInterval(float Px, float Py, float ux, float uy,
                                            float slo, float shi, float R, int y,
                                            int& xa, int& xb) {
    float dy = (float)y - Py;
    float A = uy * dy;
    float B = ux * dy;
    float dlo = -2048.f, dhi = 2048.f;
    if (fabsf(ux) > 1e-4f) {
        float i0 = (slo - A) / ux, i1 = (shi - A) / ux;
        dlo = fmaxf(dlo, fminf(i0, i1));
        dhi = fminf(dhi, fmaxf(i0, i1));
    } else if (A < slo - 0.25f || A > shi + 0.25f) return false;
    if (fabsf(uy) > 1e-4f) {
        float i0 = (B - R) / uy, i1 = (B + R) / uy;
        dlo = fmaxf(dlo, fminf(i0, i1));
        dhi = fminf(dhi, fmaxf(i0, i1));
    } else if (fabsf(B) > R + 0.25f) return false;
    xa = max(0,    (int)floorf(Px + dlo) - 1);
    xb = min(1023, (int)ceilf (Px + dhi) + 1);
    return xa <= xb;
}

__device__ __forceinline__ void sumAdd256(float v, float* dst) {
    __shared__ float sred[8];
    #pragma unroll
    for (int o = 16; o > 0; o >>= 1) v += __shfl_down_sync(0xffffffffu, v, o);
    int lane = threadIdx.x & 31, wp = threadIdx.x >> 5;
    if (lane == 0) sred[wp] = v;
    __syncthreads();
    if (threadIdx.x == 0) {
        float t = 0.f;
        #pragma unroll
        for (int i = 0; i < 8; i++) t += sred[i];
        if (t != 0.f) atomicAdd(dst, t);
    }
    __syncthreads();
}

// grid barrier across STOT resident blocks (monotonic gen -> replay-safe)
__device__ __forceinline__ void gridbar() {
    __syncthreads();
    if (threadIdx.x == 0) {
        __threadfence();
        unsigned my = *(volatile unsigned*)&g_gen;
        if (atomicAdd(&g_cnt, 1) == STOT - 1) {
            atomicExch(&g_cnt, 0);
            __threadfence();
            atomicAdd(&g_gen, 1);
        } else {
            while (*(volatile unsigned*)&g_gen == my) __nanosleep(32);
        }
        __threadfence();
    }
    __syncthreads();
}

// ---------------- k_tail: existing -> dep_sum -> deposit (1 launch) ---------
__global__ __launch_bounds__(256) void k_tail(const float* __restrict__ occ,
                                              const float* __restrict__ as_,
                                              const float* __restrict__ ae_,
                                              float* __restrict__ out) {
    const float WIDTH = 3.0f, CUT = 10.0f, EPS = 1e-8f;
    int b   = blockIdx.y;
    int blk = blockIdx.x;                 // 0..SBLK-1
    Geo g = makeGeo(as_, ae_, b);
    float msw  = __ldcg(&g_acc[b]);
    float pile = msw * (1.0f/6.0f);
    int t = threadIdx.x;
    int wp = t >> 5, lane = t & 31;
    int wrow = blk*8 + wp;                // 0..63

    // ---- phase A: existing = sum occ*probe, band s in [-CUT, pile+CUT] ----
    {
        float R   = WIDTH + CUT + 0.5f;
        float slo = -CUT - 0.5f, shi = pile + CUT + 0.5f;
        float ay = fminf(g.uy*slo, g.uy*shi) - fabsf(g.ux)*R;
        float by = fmaxf(g.uy*slo, g.uy*shi) + fabsf(g.ux)*R;
        int y0 = max(0,    (int)floorf(g.p1y + ay) - 1);
        int y1 = min(1023, (int)ceilf (g.p1y + by) + 1);

        const float* base = occ + b*IMG;
        float acc = 0.f;
        for (int y = y0 + wrow; y <= y1; y += 64) {
            int xa, xb;
            if (!rowInterval(g.p1x, g.p1y, g.ux, g.uy, slo, shi, R, y, xa, xb)) continue;
            float yf = (float)y;
            const float* row = base + y*HW;
            for (int xs = (xa & ~3) + lane*4; xs <= xb; xs += 128) {
                float4 v = *(const float4*)(row + xs);
                float rho[4] = {v.x, v.y, v.z, v.w};
                #pragma unroll
                for (int j = 0; j < 4; j++) {
                    float qx = (float)(xs + j) - g.p1x, qy = yf - g.p1y;
                    float s  = qx*g.ux + qy*g.uy;
                    float r  = qy*g.ux - qx*g.uy;
                    float ar = fabsf(r);
                    if (s > -CUT && s < pile + CUT && ar < WIDTH + CUT) {
                        float den = (1.f + __expf(-s))
                                  * (1.f + __expf(s - pile))
                                  * (1.f + __expf(ar - WIDTH));
                        acc += rho[j] * __fdividef(1.f, den);
                    }
                }
            }
        }
        sumAdd256(acc, &g_acc[NB + b]);
    }

    gridbar();
    float extra = __ldcg(&g_acc[NB + b]) * (1.0f/6.0f);

    // ---- phase B: dep_sum (compute-only) ----
    {
        float R   = WIDTH + CUT + 0.5f;
        float slo = extra - CUT - 0.5f, shi = extra + pile + CUT + 0.5f;
        float ay = fminf(g.uy*slo, g.uy*shi) - fabsf(g.ux)*R;
        float by = fmaxf(g.uy*slo, g.uy*shi) + fabsf(g.ux)*R;
        int y0 = max(0,    (int)floorf(g.p1y + ay) - 1);
        int y1 = min(1023, (int)ceilf (g.p1y + by) + 1);

        float acc = 0.f;
        for (int y = y0 + wrow; y <= y1; y += 64) {
            int xa, xb;
            if (!rowInterval(g.p1x, g.p1y, g.ux, g.uy, slo, shi, R, y, xa, xb)) continue;
            float yf = (float)y;
            for (int x = xa + lane; x <= xb; x += 32) {
                float qx = (float)x - g.p1x, qy = yf - g.p1y;
                float s  = qx*g.ux + qy*g.uy;
                float r  = qy*g.ux - qx*g.uy;
                float ar = fabsf(r);
                if (s > extra - CUT && s < extra + pile + CUT && ar < WIDTH + CUT) {
                    float den = (1.f + __expf(extra - s))
                              * (1.f + __expf(s - extra - pile))
                              * (1.f + __expf(ar - WIDTH));
                    acc += __fdividef(1.f, den);
                }
            }
        }
        sumAdd256(acc, &g_acc[2*NB + b]);
    }

    gridbar();
    float dnorm = __fdividef(msw, __ldcg(&g_acc[2*NB + b]) + EPS);

    // ---- phase C: deposit tiles (SBLK blocks/batch claim tiles round-robin) ----
    {
        const float M = CUT + 6.5f;
        float slo = extra - M, shi = extra + pile + M;
        float R   = WIDTH + M;
        float ax = g.ux*slo, bx = g.ux*shi;
        float ay = g.uy*slo, by = g.uy*shi;
        int tx0 = max(0, ((int)floorf(g.p1x + fminf(ax,bx) - fabsf(g.uy)*R)) >> 5);
        int tx1 = min(31, ((int)floorf(g.p1x + fmaxf(ax,bx) + fabsf(g.uy)*R)) >> 5);
        int ty0 = max(0, ((int)floorf(g.p1y + fminf(ay,by) - fabsf(g.ux)*R)) >> 5);
        int ty1 = min(31, ((int)floorf(g.p1y + fmaxf(ay,by) + fabsf(g.ux)*R)) >> 5);
        int nx = tx1 - tx0 + 1, ny = ty1 - ty0 + 1;
        if (nx <= 0 || ny <= 0) return;
        int nt = nx * ny;

        __shared__ float sd[40][41];
        __shared__ float sh[40][32];

        for (int idx = blk; idx < nt; idx += SBLK) {
            int tw = (tx0 + idx % nx) << 5;
            int th = (ty0 + idx / nx) << 5;

            // rotated-band tile cull (block-uniform)
            float cx = tw + 15.5f, cy = th + 15.5f;
            float qx = cx - g.p1x, qy = cy - g.p1y;
            float s  = qx*g.ux + qy*g.uy;
            float r  = qy*g.ux - qx*g.uy;
            float he = 16.5f*(fabsf(g.ux) + fabsf(g.uy)) + 6.0f;
            bool active = (s + he > extra - CUT) && (s - he < extra + pile + CUT)
                       && (fabsf(r) - he < WIDTH + CUT);
            if (!active) continue;

            for (int i = t; i < 40*40; i += 256) {
                int r_ = i / 40, c_ = i - r_*40;
                int wx = tw + c_ - 4, hy = th + r_ - 4;
                float val = 0.f;
                if ((unsigned)wx < 1024u && (unsigned)hy < 1024u) {
                    float px = (float)wx - g.p1x, py = (float)hy - g.p1y;
                    float ss = px*g.ux + py*g.uy;
                    float rr = py*g.ux - px*g.uy;
                    float ar = fabsf(rr);
                    if (ss > extra - CUT && ss < extra + pile + CUT && ar < WIDTH + CUT) {
                        float den = (1.f + __expf(extra - ss))
                                  * (1.f + __expf(ss - extra - pile))
                                  * (1.f + __expf(ar - WIDTH));
                        val = __fdividef(1.f, den);
                    }
                }
                sd[r_][c_] = val;
            }
            __syncthreads();
            for (int i = t; i < 40*32; i += 256) {
                int r_ = i >> 5, c_ = i & 31;
                float a = 0.f;
                #pragma unroll
                for (int j = 0; j < 9; j++) a = fmaf(KW[j], sd[r_][c_ + j], a);
                sh[r_][c_] = a;
            }
            __syncthreads();
            for (int i = t; i < 32*32; i += 256) {
                int r_ = i >> 5, c_ = i & 31;
                float a = 0.f;
                #pragma unroll
                for (int j = 0; j < 9; j++) a = fmaf(KW[j], sh[r_ + j][c_], a);
                int gi = b*IMG + (th + r_)*HW + (tw + c_);
                out[gi] += a * dnorm;
            }
            __syncthreads();
        }
    }
}

extern "C" void kernel_launch(void* const* d_in, const int* in_sizes, int n_in,
                              void* d_out, int out_size) {
    const float* occ = (const float*)d_in[0];
    const float* as_ = (const float*)d_in[1];
    const float* ae_ = (const float*)d_in[2];
    float* out = (float*)d_out;

    void* accPtr = nullptr;
    cudaGetSymbolAddress(&accPtr, g_acc);
    cudaMemsetAsync(accPtr, 0, sizeof(float)*3*NB, 0);

    k_swept<<<dim3(8, 32, NB), 256>>>(occ, as_, ae_, out);
    k_tail <<<dim3(SBLK, NB), 256>>>(occ, as_, ae_, out);
}

// round 14
// speedup vs baseline: 1.0601x; 1.0601x over previous
#include <cuda_runtime.h>
#include <math.h>

// ---------------------------------------------------------------------------
// SplatPushModel2 — 1 memset + 4 kernels, single stream (best-measured combo):
//   memset   : zero accumulators (device symbol, graph-capturable)
//   k_swept  : out = occ*(1-swept), fused m_swept. LTS-bound (~18.8us, cap).
//   k_ext    : existing = sum occ*probe  (row-interval band scan)
//   k_dsum   : dep_sum  = sum dep_mask   (compute-only band scan)
//   k_depadd : out += blur(dep_mask)*dnorm, ONE 32x32 tile/block, 512 thr.
// Sigmoid cutoff CUT=10 -> propagated error ~1e-5 rel (tolerance 1e-3;
// measured rel_err 3.1e-6 in R12).
// ---------------------------------------------------------------------------

#define NB    16
#define HW    1024
#define IMG   (HW*HW)

__device__ __constant__ float KW[9] = {
    0.00761439f, 0.03607498f, 0.10958593f, 0.21344431f, 0.26655960f,
    0.21344431f, 0.10958593f, 0.03607498f, 0.00761439f
};

// [0..NB) m_swept, [NB..2NB) existing, [2NB..3NB) dep_sum
__device__ float g_acc[3*NB];

struct Geo { float p0x, p0y, p1x, p1y, ux, uy, L; };

__device__ __forceinline__ float clampf(float v, float lo, float hi) {
    return fminf(fmaxf(v, lo), hi);
}

__device__ __forceinline__ Geo makeGeo(const float* as_, const float* ae_, int b) {
    Geo g;
    g.p0x = as_[b*3+0]; g.p0y = as_[b*3+1];
    g.p1x = ae_[b*3+0]; g.p1y = ae_[b*3+1];
    float dx = g.p1x - g.p0x, dy = g.p1y - g.p0y;
    g.L = sqrtf(dx*dx + dy*dy + 1e-8f);
    float inv = __fdividef(1.0f, g.L);
    g.ux = dx*inv; g.uy = dy*inv;
    return g;
}

// ---------------- k_swept: big image pass + m_swept accumulation ------------
__global__ __launch_bounds__(256) void k_swept(const float* __restrict__ occ,
                                               const float* __restrict__ as_,
                                               const float* __restrict__ ae_,
                                               float* __restrict__ out) {
    const float WIDTH = 3.0f, CUT = 10.0f, EPS = 1e-8f;
    int b  = blockIdx.z;
    int w0 = blockIdx.x << 7;
    int h0 = blockIdx.y << 5;
    Geo g = makeGeo(as_, ae_, b);

    float cx = w0 + 63.5f, cy = h0 + 15.5f;
    float rxc = cx - g.p0x, ryc = cy - g.p0y;
    float tc  = clampf(rxc*g.ux + ryc*g.uy, 0.f, g.L);
    float dcx = rxc - tc*g.ux, dcy = ryc - tc*g.uy;
    float Rt  = WIDTH + CUT + 66.5f;
    bool sw_act = (dcx*dcx + dcy*dcy) < Rt*Rt;

    int t  = threadIdx.x;
    int lw = (t & 31) << 2;
    int lh = t >> 5;
    int gi = b*IMG + (h0 + lh)*HW + (w0 + lw);

    float4 v[4];
    #pragma unroll
    for (int k = 0; k < 4; k++)
        v[k] = __ldcs((const float4*)(occ + gi + k*8*HW));

    if (!sw_act) {
        #pragma unroll
        for (int k = 0; k < 4; k++)
            __stcs((float4*)(out + gi + k*8*HW), v[k]);
        return;
    }

    float acc = 0.f;
    #pragma unroll
    for (int k = 0; k < 4; k++) {
        float y  = (float)(h0 + lh + k*8);
        float ry = y - g.p0y;
        float o[4];
        float* in = (float*)&v[k];
        #pragma unroll
        for (int j = 0; j < 4; j++) {
            float x  = (float)(w0 + lw + j);
            float rx = x - g.p0x;
            float tt = clampf(rx*g.ux + ry*g.uy, 0.f, g.L);
            float ddx = rx - tt*g.ux, ddy = ry - tt*g.uy;
            float d2 = ddx*ddx + ddy*ddy + EPS;
            float R0 = WIDTH + CUT;
            float sw = 0.f;
            if (d2 < R0*R0) {
                float dist = d2 * rsqrtf(d2);
                sw = __fdividef(1.f, 1.f + __expf(dist - WIDTH));
            }
            acc += in[j] * sw;
            o[j] = in[j] * (1.f - sw);
        }
        __stcs((float4*)(out + gi + k*8*HW), make_float4(o[0], o[1], o[2], o[3]));
    }

    __shared__ float sred[8];
    #pragma unroll
    for (int o = 16; o > 0; o >>= 1) acc += __shfl_down_sync(0xffffffffu, acc, o);
    int lane = t & 31, wp = t >> 5;
    if (lane == 0) sred[wp] = acc;
    __syncthreads();
    if (t == 0) {
        float s = 0.f;
        #pragma unroll
        for (int i = 0; i < 8; i++) s += sred[i];
        if (s != 0.f) atomicAdd(&g_acc[b], s);
    }
}

// ------------- helpers -------------------------------------------------------
__device__ __forceinline__ bool rowInterval(float Px, float Py, float ux, float uy,
                                            float slo, float shi, float R, int y,
                                            int& xa, int& xb) {
    float dy = (float)y - Py;
    float A = uy * dy;
    float B = ux * dy;
    float dlo = -2048.f, dhi = 2048.f;
    if (fabsf(ux) > 1e-4f) {
        float i0 = (slo - A) / ux, i1 = (shi - A) / ux;
        dlo = fmaxf(dlo, fminf(i0, i1));
        dhi = fminf(dhi, fmaxf(i0, i1));
    } else if (A < slo - 0.25f || A > shi + 0.25f) return false;
    if (fabsf(uy) > 1e-4f) {
        float i0 = (B - R) / uy, i1 = (B + R) / uy;
        dlo = fmaxf(dlo, fminf(i0, i1));
        dhi = fminf(dhi, fmaxf(i0, i1));
    } else if (fabsf(B) > R + 0.25f) return false;
    xa = max(0,    (int)floorf(Px + dlo) - 1);
    xb = min(1023, (int)ceilf (Px + dhi) + 1);
    return xa <= xb;
}

__device__ __forceinline__ void sumAdd256(float v, float* dst) {
    __shared__ float sred[8];
    #pragma unroll
    for (int o = 16; o > 0; o >>= 1) v += __shfl_down_sync(0xffffffffu, v, o);
    int lane = threadIdx.x & 31, wp = threadIdx.x >> 5;
    if (lane == 0) sred[wp] = v;
    __syncthreads();
    if (threadIdx.x == 0) {
        float t = 0.f;
        #pragma unroll
        for (int i = 0; i < 8; i++) t += sred[i];
        if (t != 0.f) atomicAdd(dst, t);
    }
}

// ---------------- k_ext: existing = sum occ*probe ---------------------------
__global__ __launch_bounds__(256) void k_ext(const float* __restrict__ occ,
                                             const float* __restrict__ as_,
                                             const float* __restrict__ ae_) {
    const float WIDTH = 3.0f, CUT = 10.0f;
    int b   = blockIdx.y;
    int blk = blockIdx.x;
    Geo g = makeGeo(as_, ae_, b);
    float pile = g_acc[b] * (1.0f/6.0f);

    float R   = WIDTH + CUT + 0.5f;
    float slo = -CUT - 0.5f, shi = pile + CUT + 0.5f;
    float ay = fminf(g.uy*slo, g.uy*shi) - fabsf(g.ux)*R;
    float by = fmaxf(g.uy*slo, g.uy*shi) + fabsf(g.ux)*R;
    int y0 = max(0,    (int)floorf(g.p1y + ay) - 1);
    int y1 = min(1023, (int)ceilf (g.p1y + by) + 1);

    const float* base = occ + b*IMG;
    int wp = threadIdx.x >> 5, lane = threadIdx.x & 31;
    int wrow = blk*8 + wp;

    float acc = 0.f;
    for (int y = y0 + wrow; y <= y1; y += 64) {
        int xa, xb;
        if (!rowInterval(g.p1x, g.p1y, g.ux, g.uy, slo, shi, R, y, xa, xb)) continue;
        float yf = (float)y;
        const float* row = base + y*HW;
        for (int xs = (xa & ~3) + lane*4; xs <= xb; xs += 128) {
            float4 v = *(const float4*)(row + xs);
            float rho[4] = {v.x, v.y, v.z, v.w};
            #pragma unroll
            for (int j = 0; j < 4; j++) {
                float qx = (float)(xs + j) - g.p1x, qy = yf - g.p1y;
                float s  = qx*g.ux + qy*g.uy;
                float r  = qy*g.ux - qx*g.uy;
                float ar = fabsf(r);
                if (s > -CUT && s < pile + CUT && ar < WIDTH + CUT) {
                    float den = (1.f + __expf(-s))
                              * (1.f + __expf(s - pile))
                              * (1.f + __expf(ar - WIDTH));
                    acc += rho[j] * __fdividef(1.f, den);
                }
            }
        }
    }
    sumAdd256(acc, &g_acc[NB + b]);
}

// ---------------- k_dsum: dep_sum (compute-only) ----------------------------
__global__ __launch_bounds__(256) void k_dsum(const float* __restrict__ as_,
                                              const float* __restrict__ ae_) {
    const float WIDTH = 3.0f, CUT = 10.0f;
    int b   = blockIdx.y;
    int blk = blockIdx.x;
    Geo g = makeGeo(as_, ae_, b);
    float pile  = g_acc[b]      * (1.0f/6.0f);
    float extra = g_acc[NB + b] * (1.0f/6.0f);

    float R   = WIDTH + CUT + 0.5f;
    float slo = extra - CUT - 0.5f, shi = extra + pile + CUT + 0.5f;
    float ay = fminf(g.uy*slo, g.uy*shi) - fabsf(g.ux)*R;
    float by = fmaxf(g.uy*slo, g.uy*shi) + fabsf(g.ux)*R;
    int y0 = max(0,    (int)floorf(g.p1y + ay) - 1);
    int y1 = min(1023, (int)ceilf (g.p1y + by) + 1);

    int wp = threadIdx.x >> 5, lane = threadIdx.x & 31;
    int wrow = blk*8 + wp;

    float acc = 0.f;
    for (int y = y0 + wrow; y <= y1; y += 64) {
        int xa, xb;
        if (!rowInterval(g.p1x, g.p1y, g.ux, g.uy, slo, shi, R, y, xa, xb)) continue;
        float yf = (float)y;
        for (int x = xa + lane; x <= xb; x += 32) {
            float qx = (float)x - g.p1x, qy = yf - g.p1y;
            float s  = qx*g.ux + qy*g.uy;
            float r  = qy*g.ux - qx*g.uy;
            float ar = fabsf(r);
            if (s > extra - CUT && s < extra + pile + CUT && ar < WIDTH + CUT) {
                float den = (1.f + __expf(extra - s))
                          * (1.f + __expf(s - extra - pile))
                          * (1.f + __expf(ar - WIDTH));
                acc += __fdividef(1.f, den);
            }
        }
    }
    sumAdd256(acc, &g_acc[2*NB + b]);
}

// ---------------- k_depadd: one 32x32 deposit tile per block, 512 thr -------
__global__ __launch_bounds__(512) void k_depadd(float* __restrict__ out,
                                                const float* __restrict__ as_,
                                                const float* __restrict__ ae_) {
    const float WIDTH = 3.0f, CUT = 10.0f, EPS = 1e-8f;
    int b = blockIdx.z;
    Geo g = makeGeo(as_, ae_, b);
    float msw   = g_acc[b];
    float pile  = msw * (1.0f/6.0f);
    float extra = g_acc[NB + b] * (1.0f/6.0f);
    float dnorm = __fdividef(msw, g_acc[2*NB + b] + EPS);

    const float M = CUT + 6.5f;
    float slo = extra - M, shi = extra + pile + M;
    float R   = WIDTH + M;
    float ax = g.ux*slo, bx = g.ux*shi;
    float ay = g.uy*slo, by = g.uy*shi;
    int tx0 = max(0, ((int)floorf(g.p1x + fminf(ax,bx) - fabsf(g.uy)*R)) >> 5);
    int tx1 = min(31, ((int)floorf(g.p1x + fmaxf(ax,bx) + fabsf(g.uy)*R)) >> 5);
    int ty0 = max(0, ((int)floorf(g.p1y + fminf(ay,by) - fabsf(g.ux)*R)) >> 5);
    int ty1 = min(31, ((int)floorf(g.p1y + fmaxf(ay,by) + fabsf(g.ux)*R)) >> 5);

    __shared__ float sd[40][41];
    __shared__ float sh[40][32];
    int t = threadIdx.x;

    for (int ty = ty0 + (int)blockIdx.y; ty <= ty1; ty += 8)
    for (int tx = tx0 + (int)blockIdx.x; tx <= tx1; tx += 8) {
        int tw = tx << 5, th = ty << 5;

        // rotated-band tile cull (block-uniform)
        float cx = tw + 15.5f, cy = th + 15.5f;
        float qx = cx - g.p1x, qy = cy - g.p1y;
        float s  = qx*g.ux + qy*g.uy;
        float r  = qy*g.ux - qx*g.uy;
        float he = 16.5f*(fabsf(g.ux) + fabsf(g.uy)) + 6.0f;
        bool active = (s + he > extra - CUT) && (s - he < extra + pile + CUT)
                   && (fabsf(r) - he < WIDTH + CUT);
        if (!active) continue;

        for (int i = t; i < 40*40; i += 512) {
            int r_ = i / 40, c_ = i - r_*40;
            int wx = tw + c_ - 4, hy = th + r_ - 4;
            float val = 0.f;
            if ((unsigned)wx < 1024u && (unsigned)hy < 1024u) {
                float px = (float)wx - g.p1x, py = (float)hy - g.p1y;
                float ss = px*g.ux + py*g.uy;
                float rr = py*g.ux - px*g.uy;
                float ar = fabsf(rr);
                if (ss > extra - CUT && ss < extra + pile + CUT && ar < WIDTH + CUT) {
                    float den = (1.f + __expf(extra - ss))
                              * (1.f + __expf(ss - extra - pile))
                              * (1.f + __expf(ar - WIDTH));
                    val = __fdividef(1.f, den);
                }
            }
            sd[r_][c_] = val;
        }
        __syncthreads();
        for (int i = t; i < 40*32; i += 512) {
            int r_ = i >> 5, c_ = i & 31;
            float a = 0.f;
            #pragma unroll
            for (int j = 0; j < 9; j++) a = fmaf(KW[j], sd[r_][c_ + j], a);
            sh[r_][c_] = a;
        }
        __syncthreads();
        for (int i = t; i < 32*32; i += 512) {
            int r_ = i >> 5, c_ = i & 31;
            float a = 0.f;
            #pragma unroll
            for (int j = 0; j < 9; j++) a = fmaf(KW[j], sh[r_ + j][c_], a);
            int gi = b*IMG + (th + r_)*HW + (tw + c_);
            out[gi] += a * dnorm;
        }
        __syncthreads();
    }
}

extern "C" void kernel_launch(void* const* d_in, const int* in_sizes, int n_in,
                              void* d_out, int out_size) {
    const float* occ = (const float*)d_in[0];
    const float* as_ = (const float*)d_in[1];
    const float* ae_ = (const float*)d_in[2];
    float* out = (float*)d_out;

    void* accPtr = nullptr;
    cudaGetSymbolAddress(&accPtr, g_acc);
    cudaMemsetAsync(accPtr, 0, sizeof(float)*3*NB, 0);

    k_swept <<<dim3(8, 32, NB), 256>>>(occ, as_, ae_, out);
    k_ext   <<<dim3(8, NB), 256>>>(occ, as_, ae_);
    k_dsum  <<<dim3(8, NB), 256>>>(as_, ae_);
    k_depadd<<<dim3(8, 8, NB), 512>>>(out, as_, ae_);
}

// round 15
// speedup vs baseline: 1.1195x; 1.0561x over previous
#include <cuda_runtime.h>
#include <math.h>

// ---------------------------------------------------------------------------
// SplatPushModel2 — 1 memset + 4 kernels, single stream:
//   k_swept  : out = occ*(1-swept), fused m_swept. LTS-bound (~18.8us cap).
//   k_ext    : existing = sum occ*probe   (band scan, separable mask)
//   k_dsum   : dep_sum  = sum dep_mask    (band scan, separable mask)
//   k_depadd : out += blur(dep_mask)*dnorm, 1 tile/block, 512 thr,
//              G(r) smem table + F saturation-skip -> ~0-3 MUFU/px (was 4).
// mask = F(s)*G(r) EXACT separation: F=sig(sp)sig(pile-sp), G=sig(3-|r|).
// CUT=8 (ext/dsum/depadd): est. propagated err ~2e-5 (tol 1e-3).
// ---------------------------------------------------------------------------

#define NB    16
#define HW    1024
#define IMG   (HW*HW)

__device__ __constant__ float KW[9] = {
    0.00761439f, 0.03607498f, 0.10958593f, 0.21344431f, 0.26655960f,
    0.21344431f, 0.10958593f, 0.03607498f, 0.00761439f
};

// [0..NB) m_swept, [NB..2NB) existing, [2NB..3NB) dep_sum
__device__ float g_acc[3*NB];

struct Geo { float p0x, p0y, p1x, p1y, ux, uy, L; };

__device__ __forceinline__ float clampf(float v, float lo, float hi) {
    return fminf(fmaxf(v, lo), hi);
}

__device__ __forceinline__ Geo makeGeo(const float* as_, const float* ae_, int b) {
    Geo g;
    g.p0x = as_[b*3+0]; g.p0y = as_[b*3+1];
    g.p1x = ae_[b*3+0]; g.p1y = ae_[b*3+1];
    float dx = g.p1x - g.p0x, dy = g.p1y - g.p0y;
    g.L = sqrtf(dx*dx + dy*dy + 1e-8f);
    float inv = __fdividef(1.0f, g.L);
    g.ux = dx*inv; g.uy = dy*inv;
    return g;
}

// F(sp) = sigmoid(sp)*sigmoid(pile-sp); exact-to-9e-5 skip in band interior.
__device__ __forceinline__ float maskF(float sp, float pile) {
    if (sp > 10.f && pile - sp > 10.f) return 1.f;
    float e1 = __expf(-sp);
    float e2 = __expf(sp - pile);
    return __fdividef(1.f, (1.f + e1) * (1.f + e2));
}

// ---------------- k_swept: big image pass + m_swept accumulation ------------
__global__ __launch_bounds__(256) void k_swept(const float* __restrict__ occ,
                                               const float* __restrict__ as_,
                                               const float* __restrict__ ae_,
                                               float* __restrict__ out) {
    const float WIDTH = 3.0f, CUT = 10.0f, EPS = 1e-8f;
    int b  = blockIdx.z;
    int w0 = blockIdx.x << 7;
    int h0 = blockIdx.y << 5;
    Geo g = makeGeo(as_, ae_, b);

    float cx = w0 + 63.5f, cy = h0 + 15.5f;
    float rxc = cx - g.p0x, ryc = cy - g.p0y;
    float tc  = clampf(rxc*g.ux + ryc*g.uy, 0.f, g.L);
    float dcx = rxc - tc*g.ux, dcy = ryc - tc*g.uy;
    float Rt  = WIDTH + CUT + 66.5f;
    bool sw_act = (dcx*dcx + dcy*dcy) < Rt*Rt;

    int t  = threadIdx.x;
    int lw = (t & 31) << 2;
    int lh = t >> 5;
    int gi = b*IMG + (h0 + lh)*HW + (w0 + lw);

    float4 v[4];
    #pragma unroll
    for (int k = 0; k < 4; k++)
        v[k] = __ldcs((const float4*)(occ + gi + k*8*HW));

    if (!sw_act) {
        #pragma unroll
        for (int k = 0; k < 4; k++)
            __stcs((float4*)(out + gi + k*8*HW), v[k]);
        return;
    }

    float acc = 0.f;
    #pragma unroll
    for (int k = 0; k < 4; k++) {
        float y  = (float)(h0 + lh + k*8);
        float ry = y - g.p0y;
        float o[4];
        float* in = (float*)&v[k];
        #pragma unroll
        for (int j = 0; j < 4; j++) {
            float x  = (float)(w0 + lw + j);
            float rx = x - g.p0x;
            float tt = clampf(rx*g.ux + ry*g.uy, 0.f, g.L);
            float ddx = rx - tt*g.ux, ddy = ry - tt*g.uy;
            float d2 = ddx*ddx + ddy*ddy + EPS;
            float R0 = WIDTH + CUT;
            float sw = 0.f;
            if (d2 < R0*R0) {
                float dist = d2 * rsqrtf(d2);
                sw = __fdividef(1.f, 1.f + __expf(dist - WIDTH));
            }
            acc += in[j] * sw;
            o[j] = in[j] * (1.f - sw);
        }
        __stcs((float4*)(out + gi + k*8*HW), make_float4(o[0], o[1], o[2], o[3]));
    }

    __shared__ float sred[8];
    #pragma unroll
    for (int o = 16; o > 0; o >>= 1) acc += __shfl_down_sync(0xffffffffu, acc, o);
    int lane = t & 31, wp = t >> 5;
    if (lane == 0) sred[wp] = acc;
    __syncthreads();
    if (t == 0) {
        float s = 0.f;
        #pragma unroll
        for (int i = 0; i < 8; i++) s += sred[i];
        if (s != 0.f) atomicAdd(&g_acc[b], s);
    }
}

// ------------- helpers -------------------------------------------------------
__device__ __forceinline__ bool rowInterval(float Px, float Py, float ux, float uy,
                                            float slo, float shi, float R, int y,
                                            int& xa, int& xb) {
    float dy = (float)y - Py;
    float A = uy * dy;
    float B = ux * dy;
    float dlo = -2048.f, dhi = 2048.f;
    if (fabsf(ux) > 1e-4f) {
        float i0 = (slo - A) / ux, i1 = (shi - A) / ux;
        dlo = fmaxf(dlo, fminf(i0, i1));
        dhi = fminf(dhi, fmaxf(i0, i1));
    } else if (A < slo - 0.25f || A > shi + 0.25f) return false;
    if (fabsf(uy) > 1e-4f) {
        float i0 = (B - R) / uy, i1 = (B + R) / uy;
        dlo = fmaxf(dlo, fminf(i0, i1));
        dhi = fminf(dhi, fmaxf(i0, i1));
    } else if (fabsf(B) > R + 0.25f) return false;
    xa = max(0,    (int)floorf(Px + dlo) - 1);
    xb = min(1023, (int)ceilf (Px + dhi) + 1);
    return xa <= xb;
}

__device__ __forceinline__ void sumAdd256(float v, float* dst) {
    __shared__ float sred[8];
    #pragma unroll
    for (int o = 16; o > 0; o >>= 1) v += __shfl_down_sync(0xffffffffu, v, o);
    int lane = threadIdx.x & 31, wp = threadIdx.x >> 5;
    if (lane == 0) sred[wp] = v;
    __syncthreads();
    if (threadIdx.x == 0) {
        float t = 0.f;
        #pragma unroll
        for (int i = 0; i < 8; i++) t += sred[i];
        if (t != 0.f) atomicAdd(dst, t);
    }
}

// ---------------- k_ext: existing = sum occ*probe ---------------------------
__global__ __launch_bounds__(256) void k_ext(const float* __restrict__ occ,
                                             const float* __restrict__ as_,
                                             const float* __restrict__ ae_) {
    const float WIDTH = 3.0f, CUT = 8.0f;
    int b   = blockIdx.y;
    int blk = blockIdx.x;
    Geo g = makeGeo(as_, ae_, b);
    float pile = g_acc[b] * (1.0f/6.0f);

    float R   = WIDTH + CUT + 0.5f;
    float slo = -CUT - 0.5f, shi = pile + CUT + 0.5f;
    float ay = fminf(g.uy*slo, g.uy*shi) - fabsf(g.ux)*R;
    float by = fmaxf(g.uy*slo, g.uy*shi) + fabsf(g.ux)*R;
    int y0 = max(0,    (int)floorf(g.p1y + ay) - 1);
    int y1 = min(1023, (int)ceilf (g.p1y + by) + 1);

    const float* base = occ + b*IMG;
    int wp = threadIdx.x >> 5, lane = threadIdx.x & 31;
    int wrow = blk*8 + wp;

    float acc = 0.f;
    for (int y = y0 + wrow; y <= y1; y += 64) {
        int xa, xb;
        if (!rowInterval(g.p1x, g.p1y, g.ux, g.uy, slo, shi, R, y, xa, xb)) continue;
        float yf = (float)y;
        const float* row = base + y*HW;
        for (int xs = (xa & ~3) + lane*4; xs <= xb; xs += 128) {
            float4 v = *(const float4*)(row + xs);
            float rho[4] = {v.x, v.y, v.z, v.w};
            #pragma unroll
            for (int j = 0; j < 4; j++) {
                float qx = (float)(xs + j) - g.p1x, qy = yf - g.p1y;
                float s  = qx*g.ux + qy*g.uy;
                float r  = qy*g.ux - qx*g.uy;
                float ar = fabsf(r);
                if (s > -CUT && s < pile + CUT && ar < WIDTH + CUT) {
                    float G = __fdividef(1.f, 1.f + __expf(ar - WIDTH));
                    acc += rho[j] * maskF(s, pile) * G;
                }
            }
        }
    }
    sumAdd256(acc, &g_acc[NB + b]);
}

// ---------------- k_dsum: dep_sum (compute-only) ----------------------------
__global__ __launch_bounds__(256) void k_dsum(const float* __restrict__ as_,
                                              const float* __restrict__ ae_) {
    const float WIDTH = 3.0f, CUT = 8.0f;
    int b   = blockIdx.y;
    int blk = blockIdx.x;
    Geo g = makeGeo(as_, ae_, b);
    float pile  = g_acc[b]      * (1.0f/6.0f);
    float extra = g_acc[NB + b] * (1.0f/6.0f);

    float R   = WIDTH + CUT + 0.5f;
    float slo = extra - CUT - 0.5f, shi = extra + pile + CUT + 0.5f;
    float ay = fminf(g.uy*slo, g.uy*shi) - fabsf(g.ux)*R;
    float by = fmaxf(g.uy*slo, g.uy*shi) + fabsf(g.ux)*R;
    int y0 = max(0,    (int)floorf(g.p1y + ay) - 1);
    int y1 = min(1023, (int)ceilf (g.p1y + by) + 1);

    int wp = threadIdx.x >> 5, lane = threadIdx.x & 31;
    int wrow = blk*8 + wp;

    float acc = 0.f;
    for (int y = y0 + wrow; y <= y1; y += 64) {
        int xa, xb;
        if (!rowInterval(g.p1x, g.p1y, g.ux, g.uy, slo, shi, R, y, xa, xb)) continue;
        float yf = (float)y;
        for (int x = xa + lane; x <= xb; x += 32) {
            float qx = (float)x - g.p1x, qy = yf - g.p1y;
            float s  = qx*g.ux + qy*g.uy;
            float r  = qy*g.ux - qx*g.uy;
            float ar = fabsf(r);
            float sp = s - extra;
            if (sp > -CUT && sp < pile + CUT && ar < WIDTH + CUT) {
                float G = __fdividef(1.f, 1.f + __expf(ar - WIDTH));
                acc += maskF(sp, pile) * G;
            }
        }
    }
    sumAdd256(acc, &g_acc[2*NB + b]);
}

// ---------------- k_depadd: one 32x32 deposit tile per block, 512 thr -------
__global__ __launch_bounds__(512) void k_depadd(float* __restrict__ out,
                                                const float* __restrict__ as_,
                                                const float* __restrict__ ae_) {
    const float WIDTH = 3.0f, CUT = 8.0f, EPS = 1e-8f;
    int b = blockIdx.z;
    Geo g = makeGeo(as_, ae_, b);
    float msw   = g_acc[b];
    float pile  = msw * (1.0f/6.0f);
    float extra = g_acc[NB + b] * (1.0f/6.0f);
    float dnorm = __fdividef(msw, g_acc[2*NB + b] + EPS);

    const float M = CUT + 6.5f;
    float slo = extra - M, shi = extra + pile + M;
    float R   = WIDTH + M;
    float ax = g.ux*slo, bx = g.ux*shi;
    float ay = g.uy*slo, by = g.uy*shi;
    int tx0 = max(0, ((int)floorf(g.p1x + fminf(ax,bx) - fabsf(g.uy)*R)) >> 5);
    int tx1 = min(31, ((int)floorf(g.p1x + fmaxf(ax,bx) + fabsf(g.uy)*R)) >> 5);
    int ty0 = max(0, ((int)floorf(g.p1y + fminf(ay,by) - fabsf(g.ux)*R)) >> 5);
    int ty1 = min(31, ((int)floorf(g.p1y + fmaxf(ay,by) + fabsf(g.ux)*R)) >> 5);
    if (ty0 + (int)blockIdx.y > ty1 || tx0 + (int)blockIdx.x > tx1) return;

    __shared__ float Gt[184];        // G(r) = sigmoid(3 - r), r = i/16
    __shared__ float sd[40][41];
    __shared__ float sh[40][32];
    int t = threadIdx.x;

    if (t < 184) {
        float rr = (float)t * (1.0f/16.0f);
        Gt[t] = __fdividef(1.f, 1.f + __expf(rr - WIDTH));
    }
    __syncthreads();

    for (int ty = ty0 + (int)blockIdx.y; ty <= ty1; ty += 8)
    for (int tx = tx0 + (int)blockIdx.x; tx <= tx1; tx += 8) {
        int tw = tx << 5, th = ty << 5;

        // rotated-band tile cull (block-uniform)
        float cx = tw + 15.5f, cy = th + 15.5f;
        float qx = cx - g.p1x, qy = cy - g.p1y;
        float s  = qx*g.ux + qy*g.uy;
        float r  = qy*g.ux - qx*g.uy;
        float he = 16.5f*(fabsf(g.ux) + fabsf(g.uy)) + 6.0f;
        bool active = (s + he > extra - CUT) && (s - he < extra + pile + CUT)
                   && (fabsf(r) - he < WIDTH + CUT);
        if (!active) continue;

        // prefetch RMW targets early (hide global latency under compute)
        int r0 = t >> 5,          c0 = t & 31;
        int r1 = (t + 512) >> 5,  c1 = t & 31;
        int gi0 = b*IMG + (th + r0)*HW + (tw + c0);
        int gi1 = b*IMG + (th + r1)*HW + (tw + c1);
        float o0 = out[gi0];
        float o1 = out[gi1];

        for (int i = t; i < 40*40; i += 512) {
            int r_ = i / 40, c_ = i - r_*40;
            int wx = tw + c_ - 4, hy = th + r_ - 4;
            float val = 0.f;
            if ((unsigned)wx < 1024u && (unsigned)hy < 1024u) {
                float px = (float)wx - g.p1x, py = (float)hy - g.p1y;
                float ss = px*g.ux + py*g.uy;
                float rr = py*g.ux - px*g.uy;
                float ar = fabsf(rr);
                float sp = ss - extra;
                if (sp > -CUT && sp < pile + CUT && ar < WIDTH + CUT) {
                    float kf = ar * 16.f;
                    int   k0 = (int)kf;
                    float fr = kf - (float)k0;
                    float G  = fmaf(fr, Gt[k0+1] - Gt[k0], Gt[k0]);
                    val = maskF(sp, pile) * G;
                }
            }
            sd[r_][c_] = val;
        }
        __syncthreads();
        for (int i = t; i < 40*32; i += 512) {
            int r_ = i >> 5, c_ = i & 31;
            float a = 0.f;
            #pragma unroll
            for (int j = 0; j < 9; j++) a = fmaf(KW[j], sd[r_][c_ + j], a);
            sh[r_][c_] = a;
        }
        __syncthreads();
        {
            float a0 = 0.f, a1 = 0.f;
            #pragma unroll
            for (int j = 0; j < 9; j++) {
                a0 = fmaf(KW[j], sh[r0 + j][c0], a0);
                a1 = fmaf(KW[j], sh[r1 + j][c1], a1);
            }
            out[gi0] = o0 + a0 * dnorm;
            out[gi1] = o1 + a1 * dnorm;
        }
        __syncthreads();
    }
}

extern "C" void kernel_launch(void* const* d_in, const int* in_sizes, int n_in,
                              void* d_out, int out_size) {
    const float* occ = (const float*)d_in[0];
    const float* as_ = (const float*)d_in[1];
    const float* ae_ = (const float*)d_in[2];
    float* out = (float*)d_out;

    void* accPtr = nullptr;
    cudaGetSymbolAddress(&accPtr, g_acc);
    cudaMemsetAsync(accPtr, 0, sizeof(float)*3*NB, 0);

    k_swept <<<dim3(8, 32, NB), 256>>>(occ, as_, ae_, out);
    k_ext   <<<dim3(8, NB), 256>>>(occ, as_, ae_);
    k_dsum  <<<dim3(8, NB), 256>>>(as_, ae_);
    k_depadd<<<dim3(8, 8, NB), 512>>>(out, as_, ae_);
}